// round 11
// baseline (speedup 1.0000x reference)
#include <cuda_runtime.h>
#include <cstdint>

// MTF_68461778698457: Markov Transition Field
// x: (N=4096, C=4, L=256) f32  ->  out: (N, C, 65, 65) f32
//
// One WARP per row, 8 rows per CTA. 32-bit orderable-float register bitonic
// sort + binary-search rank recovery (original positions known statically).
// Rows containing exact duplicate floats (~1e-3 of rows) take an exact O(L^2)
// stable-rank slow path, preserving bit-exactness. Phase 2: warp-local u8
// histogram with match_any dedup, single coalesced float4 output stream.
//
// Numerics (locked, rel_err == 0.0): reference division == classical
// div.full.f32 Newton expansion; refined reciprocal r1(b) hoisted, mul.rn.

constexpr int L    = 256;
constexpr int NB   = 65;
constexpr int NB2  = NB * NB;        // 4225
constexpr int RPC  = 8;              // rows per CTA (one per warp)
constexpr int HPAD = 4352;           // u8 hist row, 16B multiple, > 4225+4
constexpr int SENT = 4300;           // sentinel code for invalid transitions
constexpr unsigned int INVK = 0xFFFFFFFFu;   // key of invalid elements

__device__ __forceinline__ float refined_rcp(float b)
{
    float r;
    asm("{\n\t"
        ".reg .f32 r0, e;\n\t"
        "rcp.approx.f32 r0, %1;\n\t"
        "fma.rn.f32 e, %1, r0, 0fBF800000;\n\t"   // e' = b*r0 - 1
        "neg.f32 e, e;\n\t"                        // e  = 1 - b*r0
        "fma.rn.f32 %0, r0, e, r0;\n\t"            // r1 = r0 + r0*e
        "}"
        : "=f"(r) : "f"(b));
    return r;
}

// Exact u8 -> f32 without I2F: bits(2^23 + c) == 0x4B000000 | c for c<256.
__device__ __forceinline__ float u8_to_f32(unsigned int packed, int sel)
{
    unsigned int b = __byte_perm(packed, 0x4B000000u, 0x7540 + sel);
    return __uint_as_float(b) - 8388608.0f;
}

// Exact small-int (0..255) -> f32 without I2F.
__device__ __forceinline__ float u8i_to_f32(int r)
{
    return __uint_as_float(0x4B000000u + (unsigned int)r) - 8388608.0f;
}

__global__ __launch_bounds__(256)
void mtf_kernel(const float* __restrict__ x, float* __restrict__ out)
{
    __shared__ __align__(16) unsigned char shist[RPC][HPAD];  // 34.8 KB
    __shared__ __align__(16) unsigned char sbin[RPC][272];    //  2.2 KB
    __shared__ __align__(16) unsigned int  ssrt[RPC][L];      //  8.0 KB

    const int t    = threadIdx.x;
    const int w    = t >> 5;
    const int lane = t & 31;
    const long long rowg = (long long)blockIdx.x * RPC + w;

    // ---- zero this warp's u8 histogram (warp-private) ---------------------
    {
        uint4* h4 = (uint4*)shist[w];
        const uint4 z = make_uint4(0u, 0u, 0u, 0u);
        #pragma unroll
        for (int i = lane; i < HPAD / 16; i += 32) h4[i] = z;
    }

    // ---- Phase 1: load, range scan ----------------------------------------
    const float* xr = x + rowg * L + lane * 8;
    float4 va = *(const float4*)(xr);
    float4 vb = *(const float4*)(xr + 4);
    float v[8] = { va.x, va.y, va.z, va.w, vb.x, vb.y, vb.z, vb.w };

    int locF = 256, locE = -1;
    #pragma unroll
    for (int i = 0; i < 8; i++) {
        int idx = lane * 8 + i;
        if (v[i] != 0.0f) {
            if (idx < locF) locF = idx;
            if (idx > locE) locE = idx;
        }
    }
    const int first = __reduce_min_sync(0xffffffffu, locF);
    const int last  = __reduce_max_sync(0xffffffffu, locE);
    const bool has  = (last >= first);
    const int  vl   = has ? (last - first + 1) : 1;

    // 32-bit orderable keys; invalid -> 0xFFFFFFFF (valid data can't produce
    // it: that would require NaN input). Keep originals for rank recovery.
    unsigned int okey[8], key[8];
    #pragma unroll
    for (int i = 0; i < 8; i++) {
        int idx = lane * 8 + i;
        unsigned int u = __float_as_uint(v[i]);
        unsigned int o = (u & 0x80000000u) ? ~u : (u | 0x80000000u);
        bool valid = has && (idx >= first) && (idx <= last);
        okey[i] = valid ? o : INVK;
        key[i]  = okey[i];
    }

    // ---- u32 register bitonic sort (min/max compare-exchange) -------------
    #define CE(a, b, asc)                                                    \
        do {                                                                 \
            unsigned int _lo = umin(key[a], key[b]);                         \
            unsigned int _hi = umax(key[a], key[b]);                         \
            key[a] = (asc) ? _lo : _hi;                                      \
            key[b] = (asc) ? _hi : _lo;                                      \
        } while (0)

    #define STAGE_SHFL(off, asc)                                             \
        do {                                                                 \
            bool _keepMin = ((asc) == ((lane & (off)) == 0));                \
            _Pragma("unroll")                                                \
            for (int _i = 0; _i < 8; _i++) {                                 \
                unsigned int _o =                                            \
                    __shfl_xor_sync(0xffffffffu, key[_i], (off));            \
                key[_i] = _keepMin ? umin(key[_i], _o) : umax(key[_i], _o);  \
            }                                                                \
        } while (0)

    #define LOCAL3(asc)                                                      \
        do {                                                                 \
            CE(0,4,asc); CE(1,5,asc); CE(2,6,asc); CE(3,7,asc);              \
            CE(0,2,asc); CE(1,3,asc); CE(4,6,asc); CE(5,7,asc);              \
            CE(0,1,asc); CE(2,3,asc); CE(4,5,asc); CE(6,7,asc);              \
        } while (0)

    CE(0,1,true); CE(2,3,false); CE(4,5,true); CE(6,7,false);
    CE(0,2,true); CE(1,3,true);  CE(4,6,false); CE(5,7,false);
    CE(0,1,true); CE(2,3,true);  CE(4,5,false); CE(6,7,false);
    { bool a = (lane & 1) == 0; LOCAL3(a); }
    { bool a = (lane & 2) == 0; STAGE_SHFL(1, a); LOCAL3(a); }
    { bool a = (lane & 4) == 0; STAGE_SHFL(2, a); STAGE_SHFL(1, a); LOCAL3(a); }
    { bool a = (lane & 8) == 0; STAGE_SHFL(4, a); STAGE_SHFL(2, a);
      STAGE_SHFL(1, a); LOCAL3(a); }
    { bool a = (lane & 16) == 0; STAGE_SHFL(8, a); STAGE_SHFL(4, a);
      STAGE_SHFL(2, a); STAGE_SHFL(1, a); LOCAL3(a); }
    { STAGE_SHFL(16, true); STAGE_SHFL(8, true); STAGE_SHFL(4, true);
      STAGE_SHFL(2, true); STAGE_SHFL(1, true); LOCAL3(true); }

    #undef CE
    #undef STAGE_SHFL
    #undef LOCAL3

    // duplicate detection among VALID keys (all-invalid are identical INVK,
    // harmless). Checks all adjacent sorted pairs.
    bool dupl = false;
    #pragma unroll
    for (int i = 0; i < 7; i++)
        dupl |= (key[i] == key[i + 1]) && (key[i] != INVK);
    {
        unsigned int nxt0 = __shfl_down_sync(0xffffffffu, key[0], 1);
        if (lane < 31) dupl |= (key[7] == nxt0) && (key[7] != INVK);
    }
    const bool anydup = __any_sync(0xffffffffu, dupl);

    // store sorted keys (fast path) or original-order keys (slow path)
    {
        uint4* s4 = (uint4*)ssrt[w];
        if (!anydup) {
            s4[lane * 2 + 0] = make_uint4(key[0], key[1], key[2], key[3]);
            s4[lane * 2 + 1] = make_uint4(key[4], key[5], key[6], key[7]);
        } else {
            s4[lane * 2 + 0] = make_uint4(okey[0], okey[1], okey[2], okey[3]);
            s4[lane * 2 + 1] = make_uint4(okey[4], okey[5], okey[6], okey[7]);
        }
    }
    __syncwarp();

    // ---- rank + bin each original element (position lane*8+i) ------------
    {
        const float rinv = refined_rcp((float)vl);        // r1(vl)
        const unsigned int* srow = ssrt[w];

        if (!anydup) {
            // keys unique: rank = lower_bound in sorted array (8 probes)
            #pragma unroll
            for (int i = 0; i < 8; i++) {
                if (okey[i] != INVK) {
                    const unsigned int k = okey[i];
                    int r = 0;
                    #pragma unroll
                    for (int st = 128; st >= 1; st >>= 1)
                        r += (srow[r + st - 1] < k) ? st : 0;
                    float q  = __fmul_rn(u8i_to_f32(r), rinv); // div.full(r,vl)
                    float rb = __fmul_rn(q, 65.0f);
                    int bi = (int)rb;
                    bi = bi > (NB - 1) ? (NB - 1) : bi;
                    sbin[w][lane * 8 + i] = (unsigned char)bi;
                }
            }
        } else {
            // exact stable rank: #(kj < ki) + #(kj == ki && j < idx)
            #pragma unroll
            for (int i = 0; i < 8; i++) {
                if (okey[i] != INVK) {
                    const unsigned int k = okey[i];
                    const int idx = lane * 8 + i;
                    int r = 0;
                    for (int j = 0; j < L; j++) {
                        unsigned int kj = srow[j];
                        r += (kj < k) || (kj == k && j < idx);
                    }
                    float q  = __fmul_rn(u8i_to_f32(r), rinv);
                    float rb = __fmul_rn(q, 65.0f);
                    int bi = (int)rb;
                    bi = bi > (NB - 1) ? (NB - 1) : bi;
                    sbin[w][idx] = (unsigned char)bi;
                }
            }
        }
    }
    __syncwarp();        // sbin + zeroed hist visible within warp

    // ---- Phase 2 (warp-local): codes, match-dedup u8 hist -----------------
    int code[8];
    {
        const uint2 bw = *(const uint2*)&sbin[w][lane * 8];
        const unsigned int b8 = sbin[w][lane * 8 + 8];    // padded row, safe
        const int bl[8] = {
            (int)( bw.x        & 0xffu), (int)((bw.x >>  8) & 0xffu),
            (int)((bw.x >> 16) & 0xffu), (int)((bw.x >> 24) & 0xffu),
            (int)( bw.y        & 0xffu), (int)((bw.y >>  8) & 0xffu),
            (int)((bw.y >> 16) & 0xffu), (int)((bw.y >> 24) & 0xffu)
        };
        #pragma unroll
        for (int i = 0; i < 8; i++) {
            int tt = lane * 8 + i;
            bool tr = (tt >= first) && (tt < last);       // both ends valid
            int nb = (i < 7) ? bl[i + 1] : (int)b8;
            code[i] = tr ? (bl[i] * NB + nb) : SENT;
        }
    }

    #pragma unroll
    for (int i = 0; i < 8; i++) {
        unsigned int mask = __match_any_sync(0xffffffffu, code[i]);
        int cnt = __popc(mask);
        int leader = __ffs(mask) - 1;
        if (lane == leader && code[i] != SENT) {
            shist[w][code[i]] = (unsigned char)(shist[w][code[i]] + cnt);
        }
        __syncwarp();
    }

    // ---- Stream the full row out, coalesced float4, single write ----------
    {
        int nrm = vl - 1; if (nrm < 1) nrm = 1;
        const float rnorm = refined_rcp((float)nrm);      // r1(norm)
        const size_t p0 = (size_t)rowg * NB2;
        float* op = out + p0;
        const int lead = (int)((4 - (p0 & 3)) & 3);       // floats to peel
        const int rem  = NB2 - lead;
        const int nv   = rem >> 2;                        // float4 count
        const int tail = rem & 3;
        const unsigned int* hw = (const unsigned int*)shist[w];
        const int sh = 8 * lead;

        if (lane < lead)
            op[lane] = __fmul_rn((float)shist[w][lane], rnorm);

        for (int i = lane; i < nv; i += 32) {
            unsigned int lo = hw[i];
            unsigned int hi = hw[i + 1];                  // HPAD pad: in-bounds
            unsigned int c4 = (sh == 0) ? lo : __funnelshift_r(lo, hi, sh);
            float4 wv;
            wv.x = __fmul_rn(u8_to_f32(c4, 0), rnorm);
            wv.y = __fmul_rn(u8_to_f32(c4, 1), rnorm);
            wv.z = __fmul_rn(u8_to_f32(c4, 2), rnorm);
            wv.w = __fmul_rn(u8_to_f32(c4, 3), rnorm);
            *(float4*)(op + lead + 4 * i) = wv;
        }
        if (lane < tail) {
            int f = lead + 4 * nv + lane;
            op[f] = __fmul_rn((float)shist[w][f], rnorm);
        }
    }
}

extern "C" void kernel_launch(void* const* d_in, const int* in_sizes, int n_in,
                              void* d_out, int out_size)
{
    const float* x = (const float*)d_in[0];
    float* out = (float*)d_out;
    const int nrows = in_sizes[0] / L;       // N*C = 16384 (divisible by 8)
    mtf_kernel<<<nrows / RPC, 256>>>(x, out);
}

// round 12
// speedup vs baseline: 1.0657x; 1.0657x over previous
#include <cuda_runtime.h>
#include <cstdint>

// MTF_68461778698457: Markov Transition Field
// x: (N=4096, C=4, L=256) f32  ->  out: (N, C, 65, 65) f32
//
// One WARP per row, 8 rows per CTA.
// u32 orderable-float register bitonic sort + bank-skew-padded binary-search
// rank recovery. Rows with exact duplicate floats (~0.1%) take an exact
// O(L^2) stable-rank slow path (bit-exact). The sorted buffer and okey stash
// overlay the per-warp histogram row (hist zeroed after the search), keeping
// smem at 35.3 KB -> 6 CTAs/SM.
//
// Numerics (locked, rel_err == 0.0): reference division == classical
// div.full.f32 Newton expansion; refined reciprocal r1(b) hoisted, mul.rn.

constexpr int L    = 256;
constexpr int NB   = 65;
constexpr int NB2  = NB * NB;        // 4225
constexpr int RPC  = 8;              // rows per CTA (one per warp)
constexpr int HPAD = 4240;           // u8 hist row bytes (4225+pad, 16-mult)
constexpr int SENT = 4300;           // sentinel code for invalid transitions
constexpr unsigned int INVK = 0xFFFFFFFFu;
constexpr int STASH = 288;           // word offset of okey stash in hist row

// slot skew: i + 4*(i>>5). Lane-contiguous, 16B aligned, conflict-free for
// the search's power-of-2 stride probe patterns.
__device__ __forceinline__ int skew(int i) { return i + ((i >> 5) << 2); }

__device__ __forceinline__ float refined_rcp(float b)
{
    float r;
    asm("{\n\t"
        ".reg .f32 r0, e;\n\t"
        "rcp.approx.f32 r0, %1;\n\t"
        "fma.rn.f32 e, %1, r0, 0fBF800000;\n\t"   // e' = b*r0 - 1
        "neg.f32 e, e;\n\t"                        // e  = 1 - b*r0
        "fma.rn.f32 %0, r0, e, r0;\n\t"            // r1 = r0 + r0*e
        "}"
        : "=f"(r) : "f"(b));
    return r;
}

// Exact u8 -> f32 without I2F: bits(2^23 + c) == 0x4B000000 | c for c<256.
__device__ __forceinline__ float u8_to_f32(unsigned int packed, int sel)
{
    unsigned int b = __byte_perm(packed, 0x4B000000u, 0x7540 + sel);
    return __uint_as_float(b) - 8388608.0f;
}
__device__ __forceinline__ float u8i_to_f32(int r)
{
    return __uint_as_float(0x4B000000u + (unsigned int)r) - 8388608.0f;
}

__global__ __launch_bounds__(256)
void mtf_kernel(const float* __restrict__ x, float* __restrict__ out)
{
    __shared__ __align__(16) unsigned char shist[RPC][HPAD];  // 33.1 KB
    __shared__ __align__(16) unsigned char sbin[RPC][272];    //  2.2 KB

    const int t    = threadIdx.x;
    const int w    = t >> 5;
    const int lane = t & 31;
    const long long rowg = (long long)blockIdx.x * RPC + w;

    unsigned int* hw32 = (unsigned int*)shist[w];   // word view of hist row

    // ---- Phase 1: load, range scan, u32 keys ------------------------------
    const float* xr = x + rowg * L + lane * 8;
    float4 va = *(const float4*)(xr);
    float4 vb = *(const float4*)(xr + 4);
    float v[8] = { va.x, va.y, va.z, va.w, vb.x, vb.y, vb.z, vb.w };

    int locF = 256, locE = -1;
    #pragma unroll
    for (int i = 0; i < 8; i++) {
        int idx = lane * 8 + i;
        if (v[i] != 0.0f) {
            if (idx < locF) locF = idx;
            if (idx > locE) locE = idx;
        }
    }
    const int first = __reduce_min_sync(0xffffffffu, locF);
    const int last  = __reduce_max_sync(0xffffffffu, locE);
    const bool has  = (last >= first);
    const int  vl   = has ? (last - first + 1) : 1;

    unsigned int key[8];
    #pragma unroll
    for (int i = 0; i < 8; i++) {
        int idx = lane * 8 + i;
        unsigned int u = __float_as_uint(v[i]);
        unsigned int o = (u & 0x80000000u) ? ~u : (u | 0x80000000u);
        bool valid = has && (idx >= first) && (idx <= last);
        key[i] = valid ? o : INVK;
        // stash original key; layout [i*32 + lane] -> conflict-free
        hw32[STASH + i * 32 + lane] = key[i];
    }

    // ---- u32 register bitonic sort (predicated min/max) -------------------
    #define CE(a, b, asc)                                                    \
        do {                                                                 \
            unsigned int _lo = umin(key[a], key[b]);                         \
            unsigned int _hi = umax(key[a], key[b]);                         \
            key[a] = (asc) ? _lo : _hi;                                      \
            key[b] = (asc) ? _hi : _lo;                                      \
        } while (0)

    #define STAGE_SHFL(off, asc)                                             \
        do {                                                                 \
            bool _keepMin = ((asc) == ((lane & (off)) == 0));                \
            _Pragma("unroll")                                                \
            for (int _i = 0; _i < 8; _i++) {                                 \
                unsigned int _o =                                            \
                    __shfl_xor_sync(0xffffffffu, key[_i], (off));            \
                key[_i] = _keepMin ? umin(key[_i], _o) : umax(key[_i], _o);  \
            }                                                                \
        } while (0)

    #define LOCAL3(asc)                                                      \
        do {                                                                 \
            CE(0,4,asc); CE(1,5,asc); CE(2,6,asc); CE(3,7,asc);              \
            CE(0,2,asc); CE(1,3,asc); CE(4,6,asc); CE(5,7,asc);              \
            CE(0,1,asc); CE(2,3,asc); CE(4,5,asc); CE(6,7,asc);              \
        } while (0)

    CE(0,1,true); CE(2,3,false); CE(4,5,true); CE(6,7,false);
    CE(0,2,true); CE(1,3,true);  CE(4,6,false); CE(5,7,false);
    CE(0,1,true); CE(2,3,true);  CE(4,5,false); CE(6,7,false);
    { bool a = (lane & 1) == 0; LOCAL3(a); }
    { bool a = (lane & 2) == 0; STAGE_SHFL(1, a); LOCAL3(a); }
    { bool a = (lane & 4) == 0; STAGE_SHFL(2, a); STAGE_SHFL(1, a); LOCAL3(a); }
    { bool a = (lane & 8) == 0; STAGE_SHFL(4, a); STAGE_SHFL(2, a);
      STAGE_SHFL(1, a); LOCAL3(a); }
    { bool a = (lane & 16) == 0; STAGE_SHFL(8, a); STAGE_SHFL(4, a);
      STAGE_SHFL(2, a); STAGE_SHFL(1, a); LOCAL3(a); }
    { STAGE_SHFL(16, true); STAGE_SHFL(8, true); STAGE_SHFL(4, true);
      STAGE_SHFL(2, true); STAGE_SHFL(1, true); LOCAL3(true); }

    #undef CE
    #undef STAGE_SHFL
    #undef LOCAL3

    // duplicate detection among VALID keys
    bool dupl = false;
    #pragma unroll
    for (int i = 0; i < 7; i++)
        dupl |= (key[i] == key[i + 1]) && (key[i] != INVK);
    {
        unsigned int nxt0 = __shfl_down_sync(0xffffffffu, key[0], 1);
        if (lane < 31) dupl |= (key[7] == nxt0) && (key[7] != INVK);
    }
    const bool anydup = __any_sync(0xffffffffu, dupl);

    // store to skewed buffer. Fast path: sorted keys at sorted positions.
    // Slow path: original keys at original positions (same addresses).
    {
        // lane's 8 slots are contiguous: base = lane*8 + 4*(lane>>2)
        uint4* s4 = (uint4*)(hw32 + skew(lane * 8));
        if (!anydup) {
            s4[0] = make_uint4(key[0], key[1], key[2], key[3]);
            s4[1] = make_uint4(key[4], key[5], key[6], key[7]);
        } else {
            uint4 o0, o1;
            o0.x = hw32[STASH + 0*32 + lane]; o0.y = hw32[STASH + 1*32 + lane];
            o0.z = hw32[STASH + 2*32 + lane]; o0.w = hw32[STASH + 3*32 + lane];
            o1.x = hw32[STASH + 4*32 + lane]; o1.y = hw32[STASH + 5*32 + lane];
            o1.z = hw32[STASH + 6*32 + lane]; o1.w = hw32[STASH + 7*32 + lane];
            s4[0] = o0; s4[1] = o1;
        }
    }
    __syncwarp();

    // ---- rank + bin each original element (position lane*8+i) ------------
    {
        const float rinv = refined_rcp((float)vl);        // r1(vl)

        if (!anydup) {
            #pragma unroll
            for (int i = 0; i < 8; i++) {
                unsigned int k = hw32[STASH + i * 32 + lane];
                if (k != INVK) {
                    int r = 0;
                    #pragma unroll
                    for (int st = 128; st >= 1; st >>= 1) {
                        int p = r + st - 1;
                        r += (hw32[skew(p)] < k) ? st : 0;
                    }
                    float q  = __fmul_rn(u8i_to_f32(r), rinv); // div.full
                    float rb = __fmul_rn(q, 65.0f);
                    int bi = (int)rb;
                    bi = bi > (NB - 1) ? (NB - 1) : bi;
                    sbin[w][lane * 8 + i] = (unsigned char)bi;
                }
            }
        } else {
            // exact stable rank: #(kj < ki) + #(kj == ki && j < idx)
            #pragma unroll
            for (int i = 0; i < 8; i++) {
                unsigned int k = hw32[STASH + i * 32 + lane];
                if (k != INVK) {
                    const int idx = lane * 8 + i;
                    int r = 0;
                    for (int j = 0; j < L; j++) {
                        unsigned int kj = hw32[skew(j)];
                        r += (kj < k) || (kj == k && j < idx);
                    }
                    float q  = __fmul_rn(u8i_to_f32(r), rinv);
                    float rb = __fmul_rn(q, 65.0f);
                    int bi = (int)rb;
                    bi = bi > (NB - 1) ? (NB - 1) : bi;
                    sbin[w][idx] = (unsigned char)bi;
                }
            }
        }
    }
    __syncwarp();        // searches done -> safe to reuse hist row

    // ---- zero this warp's u8 histogram (overlays the sort buffers) --------
    {
        uint4* h4 = (uint4*)shist[w];
        const uint4 z = make_uint4(0u, 0u, 0u, 0u);
        for (int i = lane; i < HPAD / 16; i += 32) h4[i] = z;
    }
    __syncwarp();

    // ---- Phase 2 (warp-local): codes, match-dedup u8 hist -----------------
    int code[8];
    {
        const uint2 bw = *(const uint2*)&sbin[w][lane * 8];
        const unsigned int b8 = sbin[w][lane * 8 + 8];    // padded row, safe
        const int bl[8] = {
            (int)( bw.x        & 0xffu), (int)((bw.x >>  8) & 0xffu),
            (int)((bw.x >> 16) & 0xffu), (int)((bw.x >> 24) & 0xffu),
            (int)( bw.y        & 0xffu), (int)((bw.y >>  8) & 0xffu),
            (int)((bw.y >> 16) & 0xffu), (int)((bw.y >> 24) & 0xffu)
        };
        #pragma unroll
        for (int i = 0; i < 8; i++) {
            int tt = lane * 8 + i;
            bool tr = (tt >= first) && (tt < last);       // both ends valid
            int nb = (i < 7) ? bl[i + 1] : (int)b8;
            code[i] = tr ? (bl[i] * NB + nb) : SENT;
        }
    }

    #pragma unroll
    for (int i = 0; i < 8; i++) {
        unsigned int mask = __match_any_sync(0xffffffffu, code[i]);
        int cnt = __popc(mask);
        int leader = __ffs(mask) - 1;
        if (lane == leader && code[i] != SENT) {
            shist[w][code[i]] = (unsigned char)(shist[w][code[i]] + cnt);
        }
        __syncwarp();
    }

    // ---- Stream the full row out, coalesced float4, single write ----------
    {
        int nrm = vl - 1; if (nrm < 1) nrm = 1;
        const float rnorm = refined_rcp((float)nrm);      // r1(norm)
        const size_t p0 = (size_t)rowg * NB2;
        float* op = out + p0;
        const int lead = (int)((4 - (p0 & 3)) & 3);       // floats to peel
        const int rem  = NB2 - lead;
        const int nv   = rem >> 2;                        // float4 count
        const int tail = rem & 3;
        const int sh   = 8 * lead;

        if (lane < lead)
            op[lane] = __fmul_rn((float)shist[w][lane], rnorm);

        for (int i = lane; i < nv; i += 32) {
            unsigned int lo = hw32[i];
            unsigned int hi = hw32[i + 1];                // HPAD pad: in-bounds
            unsigned int c4 = (sh == 0) ? lo : __funnelshift_r(lo, hi, sh);
            float4 wv;
            wv.x = __fmul_rn(u8_to_f32(c4, 0), rnorm);
            wv.y = __fmul_rn(u8_to_f32(c4, 1), rnorm);
            wv.z = __fmul_rn(u8_to_f32(c4, 2), rnorm);
            wv.w = __fmul_rn(u8_to_f32(c4, 3), rnorm);
            *(float4*)(op + lead + 4 * i) = wv;
        }
        if (lane < tail) {
            int f = lead + 4 * nv + lane;
            op[f] = __fmul_rn((float)shist[w][f], rnorm);
        }
    }
}

extern "C" void kernel_launch(void* const* d_in, const int* in_sizes, int n_in,
                              void* d_out, int out_size)
{
    const float* x = (const float*)d_in[0];
    float* out = (float*)d_out;
    const int nrows = in_sizes[0] / L;       // N*C = 16384 (divisible by 8)
    mtf_kernel<<<nrows / RPC, 256>>>(x, out);
}

// round 13
// speedup vs baseline: 1.3870x; 1.3016x over previous
#include <cuda_runtime.h>
#include <cstdint>

// MTF_68461778698457: Markov Transition Field
// x: (N=4096, C=4, L=256) f32  ->  out: (N, C, 65, 65) f32
//
// One WARP per row (8 elems/thread u64 register bitonic sort), 8 rows/CTA.
// Phase 2 warp-local: u8 histogram with match_any dedup (no atomics),
// single coalesced float4 output stream. PRMT-based u8->f32 conversions.
// Occupancy: smem trimmed to 36096B + carveout hint -> 6 CTAs/SM.
//
// Numerics (locked, rel_err == 0.0): reference division == classical
// div.full.f32 Newton expansion; refined reciprocal r1(b) hoisted, mul.rn.

constexpr int L    = 256;
constexpr int NB   = 65;
constexpr int NB2  = NB * NB;        // 4225
constexpr int RPC  = 8;              // rows per CTA (one per warp)
constexpr int HPAD = 4240;           // u8 hist row, 16B multiple, >= 4228
constexpr int SENT = 4300;           // sentinel code for invalid transitions

__device__ __forceinline__ float refined_rcp(float b)
{
    float r;
    asm("{\n\t"
        ".reg .f32 r0, e;\n\t"
        "rcp.approx.f32 r0, %1;\n\t"
        "fma.rn.f32 e, %1, r0, 0fBF800000;\n\t"   // e' = b*r0 - 1
        "neg.f32 e, e;\n\t"                        // e  = 1 - b*r0
        "fma.rn.f32 %0, r0, e, r0;\n\t"            // r1 = r0 + r0*e
        "}"
        : "=f"(r) : "f"(b));
    return r;
}

// Exact u8 -> f32 without I2F: bits(2^23 + c) == 0x4B000000 | c for c<256.
__device__ __forceinline__ float u8_to_f32(unsigned int packed, int sel)
{
    unsigned int b = __byte_perm(packed, 0x4B000000u, 0x7540 + sel);
    return __uint_as_float(b) - 8388608.0f;    // exact (float)c
}

__global__ __launch_bounds__(256, 6)
void mtf_kernel(const float* __restrict__ x, float* __restrict__ out)
{
    __shared__ __align__(16) unsigned char shist[RPC][HPAD];  // 33.1 KB
    __shared__ __align__(16) unsigned char sbin[RPC][272];    //  2.2 KB

    const int t    = threadIdx.x;
    const int w    = t >> 5;
    const int lane = t & 31;
    const long long rowg = (long long)blockIdx.x * RPC + w;

    // ---- zero this warp's u8 histogram (warp-private) ---------------------
    {
        uint4* h4 = (uint4*)shist[w];
        const uint4 z = make_uint4(0u, 0u, 0u, 0u);
        #pragma unroll
        for (int i = lane; i < HPAD / 16; i += 32) h4[i] = z;
    }

    // ---- Phase 1: load, range scan, register bitonic sort ------------------
    const float* xr = x + rowg * L + lane * 8;
    float4 va = *(const float4*)(xr);
    float4 vb = *(const float4*)(xr + 4);
    float v[8] = { va.x, va.y, va.z, va.w, vb.x, vb.y, vb.z, vb.w };

    int locF = 256, locE = -1;
    #pragma unroll
    for (int i = 0; i < 8; i++) {
        int idx = lane * 8 + i;
        if (v[i] != 0.0f) {
            if (idx < locF) locF = idx;
            if (idx > locE) locE = idx;
        }
    }
    const int first = __reduce_min_sync(0xffffffffu, locF);
    const int last  = __reduce_max_sync(0xffffffffu, locE);
    const bool has  = (last >= first);
    const int  vl   = has ? (last - first + 1) : 1;

    unsigned long long key[8];
    #pragma unroll
    for (int i = 0; i < 8; i++) {
        int idx = lane * 8 + i;
        unsigned int u = __float_as_uint(v[i]);
        unsigned int o = (u & 0x80000000u) ? ~u : (u | 0x80000000u);
        bool valid = has && (idx >= first) && (idx <= last);
        key[i] = valid ? ((((unsigned long long)o) << 32) | (unsigned)idx)
                       : 0xFFFFFFFFFFFFFFFFull;
    }

    #define CE(a, b, asc)                                                    \
        do {                                                                 \
            if ((key[a] > key[b]) == (asc)) {                                \
                unsigned long long _tmp = key[a];                            \
                key[a] = key[b]; key[b] = _tmp;                              \
            }                                                                \
        } while (0)

    #define STAGE_SHFL(off, asc)                                             \
        do {                                                                 \
            bool _keepMin = ((asc) == ((lane & (off)) == 0));                \
            _Pragma("unroll")                                                \
            for (int _i = 0; _i < 8; _i++) {                                 \
                unsigned long long _o =                                      \
                    __shfl_xor_sync(0xffffffffu, key[_i], (off));            \
                bool _take = (_o < key[_i]) == _keepMin;                     \
                key[_i] = _take ? _o : key[_i];                              \
            }                                                                \
        } while (0)

    #define LOCAL3(asc)                                                      \
        do {                                                                 \
            CE(0,4,asc); CE(1,5,asc); CE(2,6,asc); CE(3,7,asc);              \
            CE(0,2,asc); CE(1,3,asc); CE(4,6,asc); CE(5,7,asc);              \
            CE(0,1,asc); CE(2,3,asc); CE(4,5,asc); CE(6,7,asc);              \
        } while (0)

    CE(0,1,true); CE(2,3,false); CE(4,5,true); CE(6,7,false);
    CE(0,2,true); CE(1,3,true);  CE(4,6,false); CE(5,7,false);
    CE(0,1,true); CE(2,3,true);  CE(4,5,false); CE(6,7,false);
    { bool a = (lane & 1) == 0; LOCAL3(a); }
    { bool a = (lane & 2) == 0; STAGE_SHFL(1, a); LOCAL3(a); }
    { bool a = (lane & 4) == 0; STAGE_SHFL(2, a); STAGE_SHFL(1, a); LOCAL3(a); }
    { bool a = (lane & 8) == 0; STAGE_SHFL(4, a); STAGE_SHFL(2, a);
      STAGE_SHFL(1, a); LOCAL3(a); }
    { bool a = (lane & 16) == 0; STAGE_SHFL(8, a); STAGE_SHFL(4, a);
      STAGE_SHFL(2, a); STAGE_SHFL(1, a); LOCAL3(a); }
    { STAGE_SHFL(16, true); STAGE_SHFL(8, true); STAGE_SHFL(4, true);
      STAGE_SHFL(2, true); STAGE_SHFL(1, true); LOCAL3(true); }

    #undef CE
    #undef STAGE_SHFL
    #undef LOCAL3

    // rank of element in key[i] is 8*lane + i; valid ranks are [0, vl)
    {
        const float rinv = refined_rcp((float)vl);        // r1(vl)
        const float base = (float)(lane * 8);             // one I2F
        #pragma unroll
        for (int i = 0; i < 8; i++) {
            int r = lane * 8 + i;
            if (r < vl) {
                float fr = base + (float)i;               // exact FADD (<256)
                float q  = __fmul_rn(fr, rinv);           // == div.full(r,vl)
                float rb = __fmul_rn(q, 65.0f);
                int bi = (int)rb;                         // trunc
                bi = bi > (NB - 1) ? (NB - 1) : bi;
                sbin[w][key[i] & 0xffu] = (unsigned char)bi;
            }
        }
    }
    __syncwarp();        // sbin + zeroed hist visible within warp

    // ---- Phase 2 (warp-local): codes, match-dedup u8 hist -----------------
    int code[8];
    {
        const uint2 bw = *(const uint2*)&sbin[w][lane * 8];
        const unsigned int b8 = sbin[w][lane * 8 + 8];    // padded row, safe
        const int bl[8] = {
            (int)( bw.x        & 0xffu), (int)((bw.x >>  8) & 0xffu),
            (int)((bw.x >> 16) & 0xffu), (int)((bw.x >> 24) & 0xffu),
            (int)( bw.y        & 0xffu), (int)((bw.y >>  8) & 0xffu),
            (int)((bw.y >> 16) & 0xffu), (int)((bw.y >> 24) & 0xffu)
        };
        #pragma unroll
        for (int i = 0; i < 8; i++) {
            int tt = lane * 8 + i;
            bool tr = (tt >= first) && (tt < last);       // both ends valid
            int nb = (i < 7) ? bl[i + 1] : (int)b8;
            code[i] = tr ? (bl[i] * NB + nb) : SENT;
        }
    }

    #pragma unroll
    for (int i = 0; i < 8; i++) {
        unsigned int mask = __match_any_sync(0xffffffffu, code[i]);
        int cnt = __popc(mask);
        int leader = __ffs(mask) - 1;
        if (lane == leader && code[i] != SENT) {
            shist[w][code[i]] = (unsigned char)(shist[w][code[i]] + cnt);
        }
        __syncwarp();
    }

    // ---- Stream the full row out, coalesced float4, single write ----------
    {
        int nrm = vl - 1; if (nrm < 1) nrm = 1;
        const float rnorm = refined_rcp((float)nrm);      // r1(norm)
        const size_t p0 = (size_t)rowg * NB2;
        float* op = out + p0;
        const int lead = (int)((4 - (p0 & 3)) & 3);       // floats to peel
        const int rem  = NB2 - lead;
        const int nv   = rem >> 2;                        // float4 count
        const int tail = rem & 3;
        const unsigned int* hw = (const unsigned int*)shist[w];
        const int sh = 8 * lead;

        if (lane < lead)
            op[lane] = __fmul_rn((float)shist[w][lane], rnorm);

        for (int i = lane; i < nv; i += 32) {
            unsigned int lo = hw[i];
            unsigned int hi = hw[i + 1];                  // HPAD pad: in-bounds
            unsigned int c4 = (sh == 0) ? lo : __funnelshift_r(lo, hi, sh);
            float4 wv;
            wv.x = __fmul_rn(u8_to_f32(c4, 0), rnorm);
            wv.y = __fmul_rn(u8_to_f32(c4, 1), rnorm);
            wv.z = __fmul_rn(u8_to_f32(c4, 2), rnorm);
            wv.w = __fmul_rn(u8_to_f32(c4, 3), rnorm);
            *(float4*)(op + lead + 4 * i) = wv;
        }
        if (lane < tail) {
            int f = lead + 4 * nv + lane;
            op[f] = __fmul_rn((float)shist[w][f], rnorm);
        }
    }
}

extern "C" void kernel_launch(void* const* d_in, const int* in_sizes, int n_in,
                              void* d_out, int out_size)
{
    // Hint max smem carveout so 6 CTAs/SM fit (host attribute, graph-safe,
    // no allocation). Idempotent; errors ignored (hint only).
    cudaFuncSetAttribute(mtf_kernel,
                         cudaFuncAttributePreferredSharedMemoryCarveout, 100);

    const float* x = (const float*)d_in[0];
    float* out = (float*)d_out;
    const int nrows = in_sizes[0] / L;       // N*C = 16384 (divisible by 8)
    mtf_kernel<<<nrows / RPC, 256>>>(x, out);
}